// round 1
// baseline (speedup 1.0000x reference)
#include <cuda_runtime.h>

typedef unsigned long long u64;

// ---------------- device scratch (no cudaMalloc allowed) ----------------
__device__ float g_Bmat[128 * 1024];   // [k'][ij]: k'<64 -> invSigma, k'>=64 -> -2*mu*invSigma
__device__ float g_Cc[1024];           // C[ij] = sum_k (mu^2*invSigma + log Sigma)
__device__ float g_KG[1024 * 128];     // [ij][c]: c<64 -> K, c>=64 -> v - K*mu
__device__ float g_Xext[1024 * 128];   // [b][k']: k'<64 -> X^2, k'>=64 -> X
__device__ float g_W[1024 * 1024];     // weights
__device__ float g_part[8 * 1024 * 128]; // GEMM2 k-split partials
__device__ float g_denp[8 * 1024];     // den partials per GEMM1 n-block

// ---------------- packed f32x2 helpers ----------------
__device__ __forceinline__ u64 pack2(float lo, float hi) {
    u64 r; asm("mov.b64 %0,{%1,%2};" : "=l"(r) : "f"(lo), "f"(hi)); return r;
}
__device__ __forceinline__ void unpack2(u64 v, float& lo, float& hi) {
    asm("mov.b64 {%0,%1},%2;" : "=f"(lo), "=f"(hi) : "l"(v));
}
__device__ __forceinline__ void fma2(u64& c, u64 a, u64 b) {
    asm("fma.rn.f32x2 %0,%1,%2,%0;" : "+l"(c) : "l"(a), "l"(b));
}

// ---------------- kernel 1: per-(i,j) precompute ----------------
__global__ void precompute_ij(const float* __restrict__ Mu0, const float* __restrict__ Mu1,
                              const float* __restrict__ S0, const float* __restrict__ S1,
                              const float* __restrict__ tptr) {
    int ij = blockIdx.x * blockDim.x + threadIdx.x;
    if (ij >= 1024) return;
    int i = ij >> 5, j = ij & 31;
    float t = *tptr, u = 1.0f - t;
    float Csum = 0.0f;
    #pragma unroll 4
    for (int k = 0; k < 64; k++) {
        float s0 = S0[i * 64 + k], s1 = S1[j * 64 + k];
        float m0 = Mu0[i * 64 + k], m1 = Mu1[j * 64 + k];
        float Ds = sqrtf(4.0f * s0 * s1 + 0.0625f);
        float Cs = 0.5f * (Ds - 0.25f);
        float mu = u * m0 + t * m1;
        float Sig = u * u * s0 + t * t * s1 + 2.0f * t * u * (Cs + 0.125f);
        float St = t * s1 + u * Cs - (u * s0 + t * Cs) - 0.25f * t;
        float invS = 1.0f / Sig;
        float Kv = St * invS;
        float v = m1 - m0;
        g_Bmat[k * 1024 + ij] = invS;
        g_Bmat[(64 + k) * 1024 + ij] = -2.0f * mu * invS;
        Csum += mu * mu * invS + logf(Sig);
        g_KG[ij * 128 + k] = Kv;
        g_KG[ij * 128 + 64 + k] = v - Kv * mu;
    }
    g_Cc[ij] = Csum;
}

// ---------------- kernel 1b: Xext = [X^2, X] ----------------
__global__ void build_xext(const float* __restrict__ X) {
    int idx = blockIdx.x * blockDim.x + threadIdx.x;  // 131072 total
    int b = idx >> 7, c = idx & 127;
    float x = X[b * 64 + (c & 63)];
    g_Xext[idx] = (c < 64) ? x * x : x;
}

// ---------------- kernel 2: GEMM1 (q = Xext @ Bmat) + W epilogue ----------------
// M=1024 (b), N=1024 (ij), K=128. Block tile 64x128, 256 threads, thread tile 4x8.
__global__ __launch_bounds__(256) void gemm1_kernel(const float* __restrict__ Lam) {
    __shared__ float As[32][68];    // [k][m], padded
    __shared__ float Bs[32][128];   // [k][n]
    const int tid = threadIdx.x;
    const int tx = tid & 15, ty = tid >> 4;
    const int m0 = blockIdx.x * 64, n0 = blockIdx.y * 128;

    u64 acc[4][4];
    #pragma unroll
    for (int i = 0; i < 4; i++)
        #pragma unroll
        for (int j = 0; j < 4; j++) acc[i][j] = 0ULL;

    for (int kc = 0; kc < 128; kc += 32) {
        #pragma unroll
        for (int it = 0; it < 2; it++) {
            int f = tid + it * 256;
            int r = f & 63, q = f >> 6;
            float4 v = *(const float4*)&g_Xext[(m0 + r) * 128 + kc + q * 4];
            As[q * 4 + 0][r] = v.x; As[q * 4 + 1][r] = v.y;
            As[q * 4 + 2][r] = v.z; As[q * 4 + 3][r] = v.w;
        }
        #pragma unroll
        for (int it = 0; it < 4; it++) {
            int f = tid + it * 256;
            int row = f >> 5, c4 = f & 31;
            *(float4*)&Bs[row][c4 * 4] = *(const float4*)&g_Bmat[(kc + row) * 1024 + n0 + c4 * 4];
        }
        __syncthreads();
        #pragma unroll
        for (int k = 0; k < 32; k++) {
            float4 a = *(const float4*)&As[k][ty * 4];
            u64 am[4] = {pack2(a.x, a.x), pack2(a.y, a.y), pack2(a.z, a.z), pack2(a.w, a.w)};
            const ulonglong2* bp = (const ulonglong2*)&Bs[k][tx * 8];
            ulonglong2 b01 = bp[0], b23 = bp[1];
            u64 bb[4] = {b01.x, b01.y, b23.x, b23.y};
            #pragma unroll
            for (int i = 0; i < 4; i++)
                #pragma unroll
                for (int j = 0; j < 4; j++)
                    fma2(acc[i][j], am[i], bb[j]);
        }
        __syncthreads();
    }

    // epilogue: W = exp(clip(-0.5*(q+C)))*Lam ; per-row den partials
    #pragma unroll
    for (int i = 0; i < 4; i++) {
        int m = m0 + ty * 4 + i;
        float wv[8];
        float rsum = 0.0f;
        #pragma unroll
        for (int j = 0; j < 4; j++) {
            float qlo, qhi;
            unpack2(acc[i][j], qlo, qhi);
            int ij0 = n0 + tx * 8 + 2 * j;
            float lw0 = -0.5f * (qlo + g_Cc[ij0]);
            float lw1 = -0.5f * (qhi + g_Cc[ij0 + 1]);
            lw0 = fminf(fmaxf(lw0, -50.0f), 50.0f);
            lw1 = fminf(fmaxf(lw1, -50.0f), 50.0f);
            float w0 = __expf(lw0) * Lam[ij0];
            float w1 = __expf(lw1) * Lam[ij0 + 1];
            wv[2 * j] = w0; wv[2 * j + 1] = w1;
            rsum += w0 + w1;
        }
        *(float4*)&g_W[m * 1024 + n0 + tx * 8]     = make_float4(wv[0], wv[1], wv[2], wv[3]);
        *(float4*)&g_W[m * 1024 + n0 + tx * 8 + 4] = make_float4(wv[4], wv[5], wv[6], wv[7]);
        #pragma unroll
        for (int o = 1; o < 16; o <<= 1) rsum += __shfl_xor_sync(0xffffffffu, rsum, o);
        if (tx == 0) g_denp[blockIdx.y * 1024 + m] = rsum;
    }
}

// ---------------- kernel 3: GEMM2 (ABD_partial = W @ KG), k-split=8 ----------------
// M=1024 (b), N=128 (cols of KG), K=1024 (ij) split into 8 chunks of 128.
__global__ __launch_bounds__(256) void gemm2_kernel() {
    __shared__ float As[32][68];
    __shared__ float Bs[32][128];
    const int tid = threadIdx.x;
    const int tx = tid & 15, ty = tid >> 4;
    const int m0 = blockIdx.x * 64;
    const int k0 = blockIdx.y * 128;

    u64 acc[4][4];
    #pragma unroll
    for (int i = 0; i < 4; i++)
        #pragma unroll
        for (int j = 0; j < 4; j++) acc[i][j] = 0ULL;

    for (int kc = 0; kc < 128; kc += 32) {
        #pragma unroll
        for (int it = 0; it < 2; it++) {
            int f = tid + it * 256;
            int r = f & 63, q = f >> 6;
            float4 v = *(const float4*)&g_W[(m0 + r) * 1024 + k0 + kc + q * 4];
            As[q * 4 + 0][r] = v.x; As[q * 4 + 1][r] = v.y;
            As[q * 4 + 2][r] = v.z; As[q * 4 + 3][r] = v.w;
        }
        #pragma unroll
        for (int it = 0; it < 4; it++) {
            int f = tid + it * 256;
            int row = f >> 5, c4 = f & 31;
            *(float4*)&Bs[row][c4 * 4] = *(const float4*)&g_KG[(k0 + kc + row) * 128 + c4 * 4];
        }
        __syncthreads();
        #pragma unroll
        for (int k = 0; k < 32; k++) {
            float4 a = *(const float4*)&As[k][ty * 4];
            u64 am[4] = {pack2(a.x, a.x), pack2(a.y, a.y), pack2(a.z, a.z), pack2(a.w, a.w)};
            const ulonglong2* bp = (const ulonglong2*)&Bs[k][tx * 8];
            ulonglong2 b01 = bp[0], b23 = bp[1];
            u64 bb[4] = {b01.x, b01.y, b23.x, b23.y};
            #pragma unroll
            for (int i = 0; i < 4; i++)
                #pragma unroll
                for (int j = 0; j < 4; j++)
                    fma2(acc[i][j], am[i], bb[j]);
        }
        __syncthreads();
    }

    #pragma unroll
    for (int i = 0; i < 4; i++) {
        int m = m0 + ty * 4 + i;
        float wv[8];
        #pragma unroll
        for (int j = 0; j < 4; j++) unpack2(acc[i][j], wv[2 * j], wv[2 * j + 1]);
        *(float4*)&g_part[(blockIdx.y * 1024 + m) * 128 + tx * 8]     = make_float4(wv[0], wv[1], wv[2], wv[3]);
        *(float4*)&g_part[(blockIdx.y * 1024 + m) * 128 + tx * 8 + 4] = make_float4(wv[4], wv[5], wv[6], wv[7]);
    }
}

// ---------------- kernel 4: reduce partials + final output ----------------
__global__ void final_kernel(const float* __restrict__ X, float* __restrict__ out) {
    int idx = blockIdx.x * blockDim.x + threadIdx.x;  // 65536
    int b = idx >> 6, k = idx & 63;
    float A = 0.0f, Bv = 0.0f;
    #pragma unroll
    for (int s = 0; s < 8; s++) {
        A  += g_part[(s * 1024 + b) * 128 + k];
        Bv += g_part[(s * 1024 + b) * 128 + 64 + k];
    }
    float den = 0.0f;
    #pragma unroll
    for (int s = 0; s < 8; s++) den += g_denp[s * 1024 + b];
    out[idx] = (X[idx] * A + Bv) / den;
}

// ---------------- launch ----------------
extern "C" void kernel_launch(void* const* d_in, const int* in_sizes, int n_in,
                              void* d_out, int out_size) {
    const float* X   = (const float*)d_in[0];
    const float* Mu0 = (const float*)d_in[1];
    const float* Mu1 = (const float*)d_in[2];
    const float* S0  = (const float*)d_in[3];
    const float* S1  = (const float*)d_in[4];
    const float* Lam = (const float*)d_in[5];
    const float* t   = (const float*)d_in[6];
    float* out = (float*)d_out;

    precompute_ij<<<4, 256>>>(Mu0, Mu1, S0, S1, t);
    build_xext<<<512, 256>>>(X);
    gemm1_kernel<<<dim3(16, 8), 256>>>(Lam);
    gemm2_kernel<<<dim3(16, 8), 256>>>();
    final_kernel<<<256, 256>>>(X, out);
}

// round 2
// speedup vs baseline: 2.4160x; 2.4160x over previous
#include <cuda_runtime.h>

typedef unsigned long long u64;

// ---------------- device scratch ----------------
__device__ float g_Bmat[128 * 1024];   // [k'][ij]: k'<64 -> invSigma, k'>=64 -> -2*mu*invSigma
__device__ float g_Cc[1024];           // C[ij]
__device__ float g_KG[1024 * 128];     // [ij][c]: c<64 -> K, c>=64 -> v - K*mu
__device__ float g_W[1024 * 1024];     // weights
__device__ float g_part[8 * 1024 * 128]; // GEMM2 k-split partials
__device__ float g_denp[16 * 1024];    // den partials per GEMM1 n-block

// ---------------- packed f32x2 helpers ----------------
__device__ __forceinline__ u64 pack2(float lo, float hi) {
    u64 r; asm("mov.b64 %0,{%1,%2};" : "=l"(r) : "f"(lo), "f"(hi)); return r;
}
__device__ __forceinline__ void unpack2(u64 v, float& lo, float& hi) {
    asm("mov.b64 {%0,%1},%2;" : "=f"(lo), "=f"(hi) : "l"(v));
}
__device__ __forceinline__ void fma2(u64& c, u64 a, u64 b) {
    asm("fma.rn.f32x2 %0,%1,%2,%0;" : "+l"(c) : "l"(a), "l"(b));
}

// ---------------- kernel 1: per-(i,j) precompute, warp per ij ----------------
__global__ void precompute_ij(const float* __restrict__ Mu0, const float* __restrict__ Mu1,
                              const float* __restrict__ S0, const float* __restrict__ S1,
                              const float* __restrict__ tptr) {
    int gw = (blockIdx.x * blockDim.x + threadIdx.x) >> 5;  // global warp = ij
    int lane = threadIdx.x & 31;
    if (gw >= 1024) return;
    int ij = gw;
    int i = ij >> 5, j = ij & 31;
    float t = *tptr, u = 1.0f - t;
    float Csum = 0.0f;
    #pragma unroll
    for (int kk = 0; kk < 2; kk++) {
        int k = kk * 32 + lane;
        float s0 = S0[i * 64 + k], s1 = S1[j * 64 + k];
        float m0 = Mu0[i * 64 + k], m1 = Mu1[j * 64 + k];
        float Ds = sqrtf(4.0f * s0 * s1 + 0.0625f);
        float Cs = 0.5f * (Ds - 0.25f);
        float mu = u * m0 + t * m1;
        float Sig = u * u * s0 + t * t * s1 + 2.0f * t * u * (Cs + 0.125f);
        float St = t * s1 + u * Cs - (u * s0 + t * Cs) - 0.25f * t;
        float invS = 1.0f / Sig;
        float Kv = St * invS;
        float v = m1 - m0;
        g_Bmat[k * 1024 + ij] = invS;
        g_Bmat[(64 + k) * 1024 + ij] = -2.0f * mu * invS;
        g_KG[ij * 128 + k] = Kv;
        g_KG[ij * 128 + 64 + k] = v - Kv * mu;
        Csum += mu * mu * invS + logf(Sig);
    }
    #pragma unroll
    for (int o = 16; o > 0; o >>= 1) Csum += __shfl_xor_sync(0xffffffffu, Csum, o);
    if (lane == 0) g_Cc[ij] = Csum;
}

// ---------------- GEMM1: q = Xext @ Bmat, W epilogue ----------------
// M=1024, N=1024, K=128. Tile 64x64, 256 threads, thread tile 4x4.
// A (Xext) built on the fly from X: chunks 0..3 squared, 4..7 plain.
// A stored in smem pre-duplicated as u64 {a,a}.
__global__ __launch_bounds__(256) void gemm1_kernel(const float* __restrict__ X,
                                                    const float* __restrict__ Lam) {
    __shared__ u64   As[2][16][64];  // [buf][k][m] duplicated pairs (16 KB)
    __shared__ float Bs[2][16][64];  // [buf][k][n] (8 KB)

    const int tid = threadIdx.x;
    const int tx = tid & 15, ty = tid >> 4;
    const int m0 = blockIdx.x * 64, n0 = blockIdx.y * 64;

    // staging coords
    const int sm = tid & 63;          // A: m-row
    const int sk = tid >> 6;          // A: k-seg (0..3), covers k = sk*4..sk*4+3
    const int rn = tid >> 4;          // B: k-row (0..15)
    const int cn = (tid & 15) * 4;    // B: n-col

    u64 acc[4][2];
    #pragma unroll
    for (int i = 0; i < 4; i++) { acc[i][0] = 0ULL; acc[i][1] = 0ULL; }

    // prologue: stage chunk 0
    {
        float4 va = *(const float4*)&X[(m0 + sm) * 64 + sk * 4];  // chunk0: cols 0..15, squared
        va.x *= va.x; va.y *= va.y; va.z *= va.z; va.w *= va.w;
        As[0][sk * 4 + 0][sm] = pack2(va.x, va.x);
        As[0][sk * 4 + 1][sm] = pack2(va.y, va.y);
        As[0][sk * 4 + 2][sm] = pack2(va.z, va.z);
        As[0][sk * 4 + 3][sm] = pack2(va.w, va.w);
        float4 vb = *(const float4*)&g_Bmat[rn * 1024 + n0 + cn];
        *(float4*)&Bs[0][rn][cn] = vb;
    }
    __syncthreads();

    #pragma unroll
    for (int c = 0; c < 8; c++) {
        const int p = c & 1;
        float4 va, vb;
        if (c < 7) {
            int cc = c + 1;
            va = *(const float4*)&X[(m0 + sm) * 64 + ((cc & 3) * 16 + sk * 4)];
            if (cc < 4) { va.x *= va.x; va.y *= va.y; va.z *= va.z; va.w *= va.w; }
            vb = *(const float4*)&g_Bmat[(cc * 16 + rn) * 1024 + n0 + cn];
        }
        #pragma unroll
        for (int k = 0; k < 16; k++) {
            ulonglong2 a01 = *(const ulonglong2*)&As[p][k][ty * 4];
            ulonglong2 a23 = *(const ulonglong2*)&As[p][k][ty * 4 + 2];
            ulonglong2 b   = *(const ulonglong2*)&Bs[p][k][tx * 4];
            fma2(acc[0][0], a01.x, b.x); fma2(acc[0][1], a01.x, b.y);
            fma2(acc[1][0], a01.y, b.x); fma2(acc[1][1], a01.y, b.y);
            fma2(acc[2][0], a23.x, b.x); fma2(acc[2][1], a23.x, b.y);
            fma2(acc[3][0], a23.y, b.x); fma2(acc[3][1], a23.y, b.y);
        }
        if (c < 7) {
            As[p ^ 1][sk * 4 + 0][sm] = pack2(va.x, va.x);
            As[p ^ 1][sk * 4 + 1][sm] = pack2(va.y, va.y);
            As[p ^ 1][sk * 4 + 2][sm] = pack2(va.z, va.z);
            As[p ^ 1][sk * 4 + 3][sm] = pack2(va.w, va.w);
            *(float4*)&Bs[p ^ 1][rn][cn] = vb;
            __syncthreads();
        }
    }

    // epilogue: W = exp(clip(-0.5*(q+C)))*Lam ; per-row den partials
    int ijb = n0 + tx * 4;
    float c0 = g_Cc[ijb], c1 = g_Cc[ijb + 1], c2 = g_Cc[ijb + 2], c3 = g_Cc[ijb + 3];
    float l0 = Lam[ijb], l1 = Lam[ijb + 1], l2 = Lam[ijb + 2], l3 = Lam[ijb + 3];
    #pragma unroll
    for (int i = 0; i < 4; i++) {
        int m = m0 + ty * 4 + i;
        float q0, q1, q2, q3;
        unpack2(acc[i][0], q0, q1);
        unpack2(acc[i][1], q2, q3);
        float w0 = __expf(fminf(fmaxf(-0.5f * (q0 + c0), -50.0f), 50.0f)) * l0;
        float w1 = __expf(fminf(fmaxf(-0.5f * (q1 + c1), -50.0f), 50.0f)) * l1;
        float w2 = __expf(fminf(fmaxf(-0.5f * (q2 + c2), -50.0f), 50.0f)) * l2;
        float w3 = __expf(fminf(fmaxf(-0.5f * (q3 + c3), -50.0f), 50.0f)) * l3;
        *(float4*)&g_W[m * 1024 + ijb] = make_float4(w0, w1, w2, w3);
        float rsum = (w0 + w1) + (w2 + w3);
        #pragma unroll
        for (int o = 1; o < 16; o <<= 1) rsum += __shfl_xor_sync(0xffffffffu, rsum, o);
        if (tx == 0) g_denp[blockIdx.y * 1024 + m] = rsum;
    }
}

// ---------------- GEMM2: part = W @ KG, k-split 8 ----------------
// M=1024, N=128, K=1024 split into 8x128. Tile 64x64, 256 threads.
__global__ __launch_bounds__(256) void gemm2_kernel() {
    __shared__ u64   As[2][16][64];
    __shared__ float Bs[2][16][64];

    const int tid = threadIdx.x;
    const int tx = tid & 15, ty = tid >> 4;
    const int m0 = blockIdx.x * 64, n0 = blockIdx.y * 64;
    const int k0 = blockIdx.z * 128;

    const int sm = tid & 63;
    const int sk = tid >> 6;
    const int rn = tid >> 4;
    const int cn = (tid & 15) * 4;

    u64 acc[4][2];
    #pragma unroll
    for (int i = 0; i < 4; i++) { acc[i][0] = 0ULL; acc[i][1] = 0ULL; }

    {
        float4 va = *(const float4*)&g_W[(m0 + sm) * 1024 + k0 + sk * 4];
        As[0][sk * 4 + 0][sm] = pack2(va.x, va.x);
        As[0][sk * 4 + 1][sm] = pack2(va.y, va.y);
        As[0][sk * 4 + 2][sm] = pack2(va.z, va.z);
        As[0][sk * 4 + 3][sm] = pack2(va.w, va.w);
        float4 vb = *(const float4*)&g_KG[(k0 + rn) * 128 + n0 + cn];
        *(float4*)&Bs[0][rn][cn] = vb;
    }
    __syncthreads();

    #pragma unroll
    for (int c = 0; c < 8; c++) {
        const int p = c & 1;
        float4 va, vb;
        if (c < 7) {
            int cc = c + 1;
            va = *(const float4*)&g_W[(m0 + sm) * 1024 + k0 + cc * 16 + sk * 4];
            vb = *(const float4*)&g_KG[(k0 + cc * 16 + rn) * 128 + n0 + cn];
        }
        #pragma unroll
        for (int k = 0; k < 16; k++) {
            ulonglong2 a01 = *(const ulonglong2*)&As[p][k][ty * 4];
            ulonglong2 a23 = *(const ulonglong2*)&As[p][k][ty * 4 + 2];
            ulonglong2 b   = *(const ulonglong2*)&Bs[p][k][tx * 4];
            fma2(acc[0][0], a01.x, b.x); fma2(acc[0][1], a01.x, b.y);
            fma2(acc[1][0], a01.y, b.x); fma2(acc[1][1], a01.y, b.y);
            fma2(acc[2][0], a23.x, b.x); fma2(acc[2][1], a23.x, b.y);
            fma2(acc[3][0], a23.y, b.x); fma2(acc[3][1], a23.y, b.y);
        }
        if (c < 7) {
            As[p ^ 1][sk * 4 + 0][sm] = pack2(va.x, va.x);
            As[p ^ 1][sk * 4 + 1][sm] = pack2(va.y, va.y);
            As[p ^ 1][sk * 4 + 2][sm] = pack2(va.z, va.z);
            As[p ^ 1][sk * 4 + 3][sm] = pack2(va.w, va.w);
            *(float4*)&Bs[p ^ 1][rn][cn] = vb;
            __syncthreads();
        }
    }

    #pragma unroll
    for (int i = 0; i < 4; i++) {
        int m = m0 + ty * 4 + i;
        float v0, v1, v2, v3;
        unpack2(acc[i][0], v0, v1);
        unpack2(acc[i][1], v2, v3);
        *(float4*)&g_part[(blockIdx.z * 1024 + m) * 128 + n0 + tx * 4] = make_float4(v0, v1, v2, v3);
    }
}

// ---------------- final: reduce partials + output ----------------
__global__ void final_kernel(const float* __restrict__ X, float* __restrict__ out) {
    int idx = blockIdx.x * blockDim.x + threadIdx.x;  // 65536
    int b = idx >> 6, k = idx & 63;
    float A = 0.0f, Bv = 0.0f;
    #pragma unroll
    for (int s = 0; s < 8; s++) {
        A  += g_part[(s * 1024 + b) * 128 + k];
        Bv += g_part[(s * 1024 + b) * 128 + 64 + k];
    }
    float den = 0.0f;
    #pragma unroll
    for (int s = 0; s < 16; s++) den += g_denp[s * 1024 + b];
    out[idx] = (X[idx] * A + Bv) / den;
}

// ---------------- launch ----------------
extern "C" void kernel_launch(void* const* d_in, const int* in_sizes, int n_in,
                              void* d_out, int out_size) {
    const float* X   = (const float*)d_in[0];
    const float* Mu0 = (const float*)d_in[1];
    const float* Mu1 = (const float*)d_in[2];
    const float* S0  = (const float*)d_in[3];
    const float* S1  = (const float*)d_in[4];
    const float* Lam = (const float*)d_in[5];
    const float* t   = (const float*)d_in[6];
    float* out = (float*)d_out;

    precompute_ij<<<128, 256>>>(Mu0, Mu1, S0, S1, t);
    gemm1_kernel<<<dim3(16, 16), 256>>>(X, Lam);
    gemm2_kernel<<<dim3(16, 2, 8), 256>>>();
    final_kernel<<<256, 256>>>(X, out);
}